// round 8
// baseline (speedup 1.0000x reference)
#include <cuda_runtime.h>
#include <cuda_fp16.h>
#include <cuda_bf16.h>

#define Bz 256
#define Sz 512
#define Ez 100
#define Hz 64
#define Gz 256      // 4*H
#define Vz 50000
#define VP 50048    // padded vocab rows (391*128)
#define NC 512      // 2 dirs * 256 gates

// Precomputed per-vocab input projections (+bias), fp16, layout [VP][NC]
__device__ __half g_tableh[(size_t)VP * NC];   // 51.2 MB (L2-resident)
__device__ float  g_hfin[2 * Bz * Hz];

// f32-accumulator MMA (vocab_gemm)
#define MMA16816(c0,c1,c2,c3, a0,a1,a2,a3, b0,b1) \
    asm("mma.sync.aligned.m16n8k16.row.col.f32.f16.f16.f32 " \
        "{%0,%1,%2,%3}, {%4,%5,%6,%7}, {%8,%9}, {%0,%1,%2,%3};" \
        : "+f"(c0), "+f"(c1), "+f"(c2), "+f"(c3) \
        : "r"(a0), "r"(a1), "r"(a2), "r"(a3), "r"(b0), "r"(b1))

// f16-accumulator MMA (lstm_rec): d0 = {row gid, cols 2tg..2tg+1}, d1 = row gid+8
#define MMA16816H(d0,d1, a0,a1,a2,a3, b0,b1) \
    asm("mma.sync.aligned.m16n8k16.row.col.f16.f16.f16.f16 " \
        "{%0,%1}, {%2,%3,%4,%5}, {%6,%7}, {%0,%1};" \
        : "+r"(d0), "+r"(d1) \
        : "r"(a0), "r"(a1), "r"(a2), "r"(a3), "r"(b0), "r"(b1))

// packed sigmoid: sigm(x) = 0.5*tanh(0.5x) + 0.5  (f16x2)
#define SIGM2(dst, src, h05) \
    asm("{ .reg .b32 tmp;\n\t" \
        "mul.f16x2 tmp, %1, %2;\n\t" \
        "tanh.approx.f16x2 tmp, tmp;\n\t" \
        "fma.rn.f16x2 %0, tmp, %2, %2; }" \
        : "=r"(dst) : "r"(src), "r"(h05))

__device__ __forceinline__ unsigned int tanh2_ap(unsigned int x) {
    unsigned int y;
    asm("tanh.approx.f16x2 %0, %1;" : "=r"(y) : "r"(x));
    return y;
}
__device__ __forceinline__ unsigned int hadd2u(unsigned int a, unsigned int b) {
    unsigned int d;
    asm("add.rn.f16x2 %0, %1, %2;" : "=r"(d) : "r"(a), "r"(b));
    return d;
}
__device__ __forceinline__ unsigned int hmul2u(unsigned int a, unsigned int b) {
    unsigned int d;
    asm("mul.f16x2 %0, %1, %2;" : "=r"(d) : "r"(a), "r"(b));
    return d;
}
__device__ __forceinline__ unsigned int hfma2u(unsigned int a, unsigned int b,
                                               unsigned int c) {
    unsigned int d;
    asm("fma.rn.f16x2 %0, %1, %2, %3;" : "=r"(d) : "r"(a), "r"(b), "r"(c));
    return d;
}
__device__ __forceinline__ unsigned int pkh(__half lo, __half hi) {
    __half2 h = __halves2half2(lo, hi);
    return *(unsigned int*)&h;
}

// ---------------------------------------------------------------------------
// Kernel 1: vocab-table GEMM via HMMA (fp16 in, fp32 accum, fp16 store).
//   Tile 128(M) x 64(N) x 112(K pad). 8 warps (4M x 2N). Unchanged from R6.
// ---------------------------------------------------------------------------
#define LDH 120    // smem row stride in halfs

__global__ __launch_bounds__(256)
void vocab_gemm(const float* __restrict__ emb,
                const float* __restrict__ Wih_f,
                const float* __restrict__ bih_f,
                const float* __restrict__ bhh_f,
                const float* __restrict__ Wih_b,
                const float* __restrict__ bih_b,
                const float* __restrict__ bhh_b)
{
    const int tid  = threadIdx.x;
    const int lane = tid & 31;
    const int w    = tid >> 5;
    const int gid  = lane >> 2;
    const int tg   = lane & 3;
    const int wm   = w & 3;
    const int wn   = w >> 2;

    const int rb = blockIdx.x * 128;
    const int cb = blockIdx.y * 64;
    const int dir = cb >> 8;
    const int gb  = cb & 255;

    const float* __restrict__ W  = dir ? Wih_b : Wih_f;
    const float* __restrict__ bi = dir ? bih_b : bih_f;
    const float* __restrict__ bh = dir ? bhh_b : bhh_f;

    __shared__ __align__(16) __half As[128 * LDH];
    __shared__ __align__(16) __half Bs[64 * LDH];
    __shared__ float bias_s[64];

    if (tid < 64) bias_s[tid] = bi[gb + tid] + bh[gb + tid];

    const float2* __restrict__ emb2 = (const float2*)emb;
    const float2* __restrict__ W2   = (const float2*)W;
    __half2* As2 = (__half2*)As;
    __half2* Bs2 = (__half2*)Bs;

    for (int p = tid; p < 128 * 50; p += 256) {
        int m = p / 50, q = p - m * 50;
        int row = rb + m; if (row >= Vz) row = Vz - 1;
        float2 v = emb2[(size_t)row * 50 + q];
        As2[m * (LDH / 2) + q] = __floats2half2_rn(v.x, v.y);
    }
    for (int p = tid; p < 128 * 6; p += 256) {
        int m = p / 6, q = 50 + (p - m * 6);
        As2[m * (LDH / 2) + q] = __half2half2(__float2half(0.0f));
    }
    for (int p = tid; p < 64 * 50; p += 256) {
        int m = p / 50, q = p - m * 50;
        float2 v = W2[(size_t)(gb + m) * 50 + q];
        Bs2[m * (LDH / 2) + q] = __floats2half2_rn(v.x, v.y);
    }
    for (int p = tid; p < 64 * 6; p += 256) {
        int m = p / 6, q = 50 + (p - m * 6);
        Bs2[m * (LDH / 2) + q] = __half2half2(__float2half(0.0f));
    }
    __syncthreads();

    float acc[2][4][4];
#pragma unroll
    for (int mt = 0; mt < 2; mt++)
#pragma unroll
        for (int nt = 0; nt < 4; nt++)
#pragma unroll
            for (int i = 0; i < 4; i++) acc[mt][nt][i] = 0.0f;

#pragma unroll
    for (int kt = 0; kt < 7; kt++) {
        unsigned int a[2][4], b[4][2];
#pragma unroll
        for (int mt = 0; mt < 2; mt++) {
            int r = wm * 32 + mt * 16 + gid;
            const unsigned int* p0 = (const unsigned int*)(As + r * LDH + kt * 16 + 2 * tg);
            const unsigned int* p1 = (const unsigned int*)(As + (r + 8) * LDH + kt * 16 + 2 * tg);
            a[mt][0] = p0[0];
            a[mt][1] = p1[0];
            a[mt][2] = p0[4];
            a[mt][3] = p1[4];
        }
#pragma unroll
        for (int nt = 0; nt < 4; nt++) {
            int n = wn * 32 + nt * 8 + gid;
            const unsigned int* p = (const unsigned int*)(Bs + n * LDH + kt * 16 + 2 * tg);
            b[nt][0] = p[0];
            b[nt][1] = p[4];
        }
#pragma unroll
        for (int mt = 0; mt < 2; mt++)
#pragma unroll
            for (int nt = 0; nt < 4; nt++)
                MMA16816(acc[mt][nt][0], acc[mt][nt][1], acc[mt][nt][2], acc[mt][nt][3],
                         a[mt][0], a[mt][1], a[mt][2], a[mt][3],
                         b[nt][0], b[nt][1]);
    }

#pragma unroll
    for (int mt = 0; mt < 2; mt++) {
#pragma unroll
        for (int nt = 0; nt < 4; nt++) {
            int n = wn * 32 + nt * 8 + 2 * tg;
            float b0 = bias_s[n], b1 = bias_s[n + 1];
            int r0 = rb + wm * 32 + mt * 16 + gid;
            int r1 = r0 + 8;
            *(__half2*)&g_tableh[(size_t)r0 * NC + cb + n] =
                __floats2half2_rn(acc[mt][nt][0] + b0, acc[mt][nt][1] + b1);
            *(__half2*)&g_tableh[(size_t)r1 * NC + cb + n] =
                __floats2half2_rn(acc[mt][nt][2] + b0, acc[mt][nt][3] + b1);
        }
    }
}

// ---------------------------------------------------------------------------
// Kernel 2: LSTM recurrence, f16-accumulator HMMA + fully packed update.
// 4 chains (+4 pad) per block; 128 blocks = 1 wave; 8 warps.
// Permuted-gate A packing: warp w, thread (gid,tg), cell e = 8w+gid:
//   mt0 rows: gid -> i(e), gid+8 -> f(e);  mt1: g(e), o(e).
// f16 D fragment: d0 = {gate, chains 2tg, 2tg+1} packed f16x2 == ui directly.
// Update: all f16x2 (tanh.approx.f16x2), c-state packed f16x2. 1 BAR/step.
// ---------------------------------------------------------------------------
#define HP 72    // h smem row stride (halfs)

__global__ __launch_bounds__(256)
void lstm_rec(const int* __restrict__ x,
              const float* __restrict__ Whh_f,
              const float* __restrict__ Whh_b)
{
    const int tid  = threadIdx.x;
    const int lane = tid & 31;
    const int w    = tid >> 5;
    const int gid  = lane >> 2;
    const int tg   = lane & 3;
    const int e    = w * 8 + gid;       // owned cell
    const int n0   = 2 * tg;            // chains n0, n0+1 (real if tg<2)
    const bool real = (tg < 2);

    const int bg  = blockIdx.x;
    const int dir = blockIdx.y;
    const float* __restrict__ W = dir ? Whh_b : Whh_f;

    __shared__ int toks[4][Sz];
    __shared__ __align__(16) __half h_sh[2][8 * HP];

    for (int p = tid; p < 4 * Sz; p += 256) {
        int r = p >> 9, t = p & 511;
        toks[r][t] = x[(bg * 4 + r) * Sz + t];
    }
    for (int p = tid; p < 2 * 8 * HP; p += 256)
        ((__half*)h_sh)[p] = __float2half(0.0f);

    // A fragments, permuted-gate packing, fp16
    unsigned int afr[2][4][4];
#pragma unroll
    for (int mt = 0; mt < 2; mt++) {
        const float* r0 = W + (size_t)((2 * mt)     * 64 + e) * Hz;
        const float* r1 = W + (size_t)((2 * mt + 1) * 64 + e) * Hz;
#pragma unroll
        for (int kt = 0; kt < 4; kt++) {
            int cb_ = kt * 16 + tg * 2;
            __half2 h0 = __floats2half2_rn(r0[cb_],     r0[cb_ + 1]);
            __half2 h1 = __floats2half2_rn(r1[cb_],     r1[cb_ + 1]);
            __half2 h2 = __floats2half2_rn(r0[cb_ + 8], r0[cb_ + 9]);
            __half2 h3 = __floats2half2_rn(r1[cb_ + 8], r1[cb_ + 9]);
            afr[mt][kt][0] = *(unsigned int*)&h0;
            afr[mt][kt][1] = *(unsigned int*)&h1;
            afr[mt][kt][2] = *(unsigned int*)&h2;
            afr[mt][kt][3] = *(unsigned int*)&h3;
        }
    }

    unsigned int cst = 0u;              // packed f16x2 cell state (2 chains)
    unsigned int hn  = 0u;              // packed h output

    const __half* __restrict__ tb = g_tableh + dir * Gz;

    __syncthreads();

    int t = dir ? (Sz - 1) : 0;
    const int dt = dir ? -1 : 1;

    // xp packed: xcp[0]=i pair, [1]=f, [2]=g, [3]=o  (chains n0, n0+1)
    unsigned int xcp[4] = {0u, 0u, 0u, 0u};
    if (real) {
        size_t ba = (size_t)toks[n0][t] * NC;
        size_t bb = (size_t)toks[n0 + 1][t] * NC;
        xcp[0] = pkh(tb[ba + e],       tb[bb + e]);
        xcp[1] = pkh(tb[ba + 64 + e],  tb[bb + 64 + e]);
        xcp[2] = pkh(tb[ba + 128 + e], tb[bb + 128 + e]);
        xcp[3] = pkh(tb[ba + 192 + e], tb[bb + 192 + e]);
    }

    const unsigned int H05 = 0x38003800u;  // half2(0.5, 0.5)
    int pb = 0;

#pragma unroll 1
    for (int s = 0; s < Sz; s++) {
        int tn = t + dt;
        unsigned int xnp[4] = {0u, 0u, 0u, 0u};
        if (real && s < Sz - 1) {
            size_t ba = (size_t)toks[n0][tn] * NC;
            size_t bb = (size_t)toks[n0 + 1][tn] * NC;
            xnp[0] = pkh(tb[ba + e],       tb[bb + e]);
            xnp[1] = pkh(tb[ba + 64 + e],  tb[bb + 64 + e]);
            xnp[2] = pkh(tb[ba + 128 + e], tb[bb + 128 + e]);
            xnp[3] = pkh(tb[ba + 192 + e], tb[bb + 192 + e]);
        }

        // B fragments from h_sh
        unsigned int b0[4], b1[4];
#pragma unroll
        for (int kt = 0; kt < 4; kt++) {
            const unsigned int* hw =
                (const unsigned int*)(h_sh[pb] + gid * HP + kt * 16 + tg * 2);
            b0[kt] = hw[0];
            b1[kt] = hw[4];
        }

        // Two independent 2-deep MMA chains per mt, then merge.
        unsigned int ui, uf, ug, uo;
        {
            unsigned int p0 = xcp[0], p1 = xcp[1], q0 = 0u, q1 = 0u;
            MMA16816H(p0, p1, afr[0][0][0], afr[0][0][1], afr[0][0][2], afr[0][0][3], b0[0], b1[0]);
            MMA16816H(q0, q1, afr[0][2][0], afr[0][2][1], afr[0][2][2], afr[0][2][3], b0[2], b1[2]);
            MMA16816H(p0, p1, afr[0][1][0], afr[0][1][1], afr[0][1][2], afr[0][1][3], b0[1], b1[1]);
            MMA16816H(q0, q1, afr[0][3][0], afr[0][3][1], afr[0][3][2], afr[0][3][3], b0[3], b1[3]);
            ui = hadd2u(p0, q0);
            uf = hadd2u(p1, q1);
        }
        {
            unsigned int p0 = xcp[2], p1 = xcp[3], q0 = 0u, q1 = 0u;
            MMA16816H(p0, p1, afr[1][0][0], afr[1][0][1], afr[1][0][2], afr[1][0][3], b0[0], b1[0]);
            MMA16816H(q0, q1, afr[1][2][0], afr[1][2][1], afr[1][2][2], afr[1][2][3], b0[2], b1[2]);
            MMA16816H(p0, p1, afr[1][1][0], afr[1][1][1], afr[1][1][2], afr[1][1][3], b0[1], b1[1]);
            MMA16816H(q0, q1, afr[1][3][0], afr[1][3][1], afr[1][3][2], afr[1][3][3], b0[3], b1[3]);
            ug = hadd2u(p0, q0);
            uo = hadd2u(p1, q1);
        }

        // fully packed update
        unsigned int si, sf, so;
        SIGM2(si, ui, H05);
        SIGM2(sf, uf, H05);
        SIGM2(so, uo, H05);
        unsigned int tg2 = tanh2_ap(ug);
        cst = hfma2u(sf, cst, hmul2u(si, tg2));
        hn  = hmul2u(so, tanh2_ap(cst));

        if (real) {
            __half2 hh = *(__half2*)&hn;
            h_sh[pb ^ 1][n0 * HP + e]       = __low2half(hh);
            h_sh[pb ^ 1][(n0 + 1) * HP + e] = __high2half(hh);
        }
        __syncthreads();

        pb ^= 1;
#pragma unroll
        for (int q = 0; q < 4; q++) xcp[q] = xnp[q];
        t = tn;
    }

    if (real) {
        __half2 hh = *(__half2*)&hn;
        g_hfin[(size_t)(dir * Bz + bg * 4 + n0) * Hz + e]     = __low2float(hh);
        g_hfin[(size_t)(dir * Bz + bg * 4 + n0 + 1) * Hz + e] = __high2float(hh);
    }
}

// ---------------------------------------------------------------------------
// Kernel 3: final FC + sigmoid
// ---------------------------------------------------------------------------
__global__ void final_fc(const float* __restrict__ fcw,
                         const float* __restrict__ fcb,
                         float* __restrict__ out)
{
    int b = threadIdx.x;
    if (b >= Bz) return;
    float acc = fcb[0];
    const float* hf = g_hfin + b * Hz;
    const float* hb = g_hfin + Bz * Hz + b * Hz;
#pragma unroll
    for (int u = 0; u < Hz; u++) {
        acc = fmaf(hf[u], fcw[u], acc);
        acc = fmaf(hb[u], fcw[Hz + u], acc);
    }
    out[b] = __fdividef(1.0f, 1.0f + __expf(-acc));
}

// ---------------------------------------------------------------------------
extern "C" void kernel_launch(void* const* d_in, const int* in_sizes, int n_in,
                              void* d_out, int out_size)
{
    const int*   x     = (const int*)  d_in[0];
    const float* emb   = (const float*)d_in[1];
    const float* Wih_f = (const float*)d_in[2];
    const float* Whh_f = (const float*)d_in[3];
    const float* bih_f = (const float*)d_in[4];
    const float* bhh_f = (const float*)d_in[5];
    const float* Wih_b = (const float*)d_in[6];
    const float* Whh_b = (const float*)d_in[7];
    const float* bih_b = (const float*)d_in[8];
    const float* bhh_b = (const float*)d_in[9];
    const float* fcw   = (const float*)d_in[10];
    const float* fcb   = (const float*)d_in[11];
    float* out = (float*)d_out;

    dim3 g1(VP / 128, NC / 64);   // 391 x 8
    vocab_gemm<<<g1, 256>>>(emb, Wih_f, bih_f, bhh_f, Wih_b, bih_b, bhh_b);

    dim3 g2(Bz / 4, 2);           // 128 blocks, one wave
    lstm_rec<<<g2, 256>>>(x, Whh_f, Whh_b);

    final_fc<<<1, 256>>>(fcw, fcb, out);
}